// round 1
// baseline (speedup 1.0000x reference)
#include <cuda_runtime.h>
#include <cstdint>

#define BB 16
#define AA 8400
#define GG 64
#define CC 80
#define KK 10
#define FEPS 1e-9f

// Scratch (allocation-free rule: __device__ globals)
__device__ unsigned long long g_key[BB * AA];   // packed (ciou_bits<<32)|(G-1-g) per (b,a)
__device__ unsigned int       g_normb[BB * AA]; // float bits of norm per (b,a)
__device__ int                g_maskbuf[BB * GG];

// ---------------------------------------------------------------------------
// init: zero scratch; block 0 decodes gt_mask with runtime dtype detection
// (bool/u8, int32, float32, bfloat16 all handled)
// ---------------------------------------------------------------------------
__global__ void init_kernel(const unsigned char* __restrict__ mask_raw) {
    int tid = blockIdx.x * blockDim.x + threadIdx.x;
    for (int i = tid; i < BB * AA; i += gridDim.x * blockDim.x) {
        g_key[i]   = 0ull;
        g_normb[i] = 0u;
    }
    if (blockIdx.x == 0) {
        __shared__ int s_f32, s_bf16, s_u8;
        if (threadIdx.x == 0) { s_f32 = 0; s_bf16 = 0; s_u8 = 0; }
        __syncthreads();
        // First BB*GG bytes are in-bounds for every candidate layout.
        for (int i = threadIdx.x; i < BB * GG; i += blockDim.x) {
            unsigned char byt = mask_raw[i];
            if (byt == 0x3F) {                 // exponent byte of 1.0f / 1.0bf16
                if ((i & 3) == 3) s_f32 = 1;   // f32: 0x3F only at offset 3 mod 4
                if ((i & 3) == 1) s_bf16 = 1;  // bf16: 0x3F at offset 1 mod 4 too
            }
            if (byt != 0 && (i & 3) != 0) s_u8 = 1;  // packed bools
        }
        __syncthreads();
        int mode = s_bf16 ? 3 : (s_f32 ? 2 : (s_u8 ? 0 : 1));
        for (int i = threadIdx.x; i < BB * GG; i += blockDim.x) {
            int v;
            if (mode == 0)      v = (mask_raw[i] != 0);
            else if (mode == 3) v = (((const unsigned short*)mask_raw)[i] != 0);
            else                v = (((const unsigned int*)mask_raw)[i] != 0);
            g_maskbuf[i] = v;
        }
    }
}

// ---------------------------------------------------------------------------
// CIoU, exactly mirroring the reference op order
// ---------------------------------------------------------------------------
__device__ __forceinline__ float ciou_fn(
    float gx1, float gy1, float gx2, float gy2,
    float w1, float h1, float area1, float at1,
    float dx1, float dy1, float dx2, float dy2)
{
    float xx1 = fmaxf(gx1, dx1), yy1 = fmaxf(gy1, dy1);
    float xx2 = fminf(gx2, dx2), yy2 = fminf(gy2, dy2);
    float iw = fmaxf(xx2 - xx1, 0.0f), ih = fmaxf(yy2 - yy1, 0.0f);
    float inter = iw * ih;
    float w2 = dx2 - dx1, h2 = dy2 - dy1;
    float uni = area1 + w2 * h2 - inter;
    float iou = __fdiv_rn(inter, uni + FEPS);
    float cw = fmaxf(gx2, dx2) - fminf(gx1, dx1);
    float ch = fmaxf(gy2, dy2) - fminf(gy1, dy1);
    float c2 = cw * cw + ch * ch + FEPS;
    float ex = (gx1 + gx2) - (dx1 + dx2);
    float ey = (gy1 + gy2) - (dy1 + dy2);
    float rho2 = (ex * ex + ey * ey) * 0.25f;
    float dat = at1 - atanf(__fdiv_rn(w2, h2 + FEPS));
    float v = 0.40528473456935108577f * dat * dat;  // 4/pi^2
    float al = __fdiv_rn(v, v - iou + 1.0f + FEPS);
    return iou - (__fdiv_rn(rho2, c2) + v * al);
}

// ---------------------------------------------------------------------------
// assign: one block per (b,g). Inside-test scan -> per-thread top-10 ->
// block merge -> <=10 atomics into per-anchor scratch.
// ---------------------------------------------------------------------------
__global__ __launch_bounds__(256) void assign_kernel(
    const float* __restrict__ scores, const float* __restrict__ dbox,
    const float* __restrict__ anchors, const int* __restrict__ gt_labels,
    const float* __restrict__ gt_bboxes)
{
    int bg = blockIdx.x;
    if (!g_maskbuf[bg]) return;
    int b = bg / GG, g = bg % GG;
    int tid = threadIdx.x;

    float gx1 = gt_bboxes[bg * 4 + 0], gy1 = gt_bboxes[bg * 4 + 1];
    float gx2 = gt_bboxes[bg * 4 + 2], gy2 = gt_bboxes[bg * 4 + 3];
    int label = gt_labels[bg];
    if (label < 0) label = 0;
    float w1 = gx2 - gx1, h1 = gy2 - gy1;
    float area1 = w1 * h1;
    float at1 = atanf(__fdiv_rn(w1, h1 + FEPS));

    const float* dbb = dbox + (size_t)b * AA * 4;
    const float* sb  = scores + (size_t)b * AA * CC;

    unsigned long long kk[KK];
#pragma unroll
    for (int j = 0; j < KK; j++) kk[j] = 0ull;

    for (int a = tid; a < AA; a += 256) {
        float2 an = ((const float2*)anchors)[a];
        if (gx1 < an.x && gy1 < an.y && gx2 > an.x && gy2 > an.y) {
            float4 d = ((const float4*)dbb)[a];
            float ov = ciou_fn(gx1, gy1, gx2, gy2, w1, h1, area1, at1,
                               d.x, d.y, d.z, d.w);
            if (ov > 0.0f) {
                float s = sb[a * CC + label];
                float p2 = ov * ov;
                float p6 = p2 * p2 * p2;
                float align = sqrtf(s) * p6;
                unsigned long long key =
                    ((unsigned long long)__float_as_uint(align) << 32) |
                    (unsigned int)(AA - a);  // tie-break: smaller a wins
                if (key > kk[KK - 1]) {
                    kk[KK - 1] = key;
#pragma unroll
                    for (int j = KK - 2; j >= 0; j--) {
                        unsigned long long x = kk[j], y = kk[j + 1];
                        kk[j]     = x > y ? x : y;
                        kk[j + 1] = x > y ? y : x;
                    }
                }
            }
        }
    }

    // Block-wide top-K merge by repeated strict-descending max selection.
    __shared__ unsigned long long swarp[8];
    __shared__ unsigned long long sres;
    __shared__ unsigned long long winners[KK];
    __shared__ float s_ciou[KK];
    __shared__ float s_maxovl;

    unsigned long long last = ~0ull;
    for (int k = 0; k < KK; k++) {
        unsigned long long cand = 0ull;
#pragma unroll
        for (int j = 0; j < KK; j++) {
            unsigned long long v = kk[j];
            if (v < last && v > cand) cand = v;
        }
#pragma unroll
        for (int o = 16; o; o >>= 1) {
            unsigned long long t = __shfl_down_sync(0xffffffffu, cand, o);
            if (t > cand) cand = t;
        }
        if ((tid & 31) == 0) swarp[tid >> 5] = cand;
        __syncthreads();
        if (tid == 0) {
            unsigned long long m = swarp[0];
#pragma unroll
            for (int i = 1; i < 8; i++)
                if (swarp[i] > m) m = swarp[i];
            sres = m;
            winners[k] = m;
        }
        __syncthreads();
        last = sres;
    }
    __syncthreads();

    unsigned long long wkey = (tid < KK) ? winners[tid] : 0ull;
    float my_ciou = 0.0f, my_align = 0.0f;
    int my_a = -1;
    if (tid < KK && wkey != 0ull) {
        my_a = AA - (int)(unsigned int)(wkey & 0xffffffffull);
        my_align = __uint_as_float((unsigned int)(wkey >> 32));
        float4 d = ((const float4*)dbb)[my_a];
        my_ciou = ciou_fn(gx1, gy1, gx2, gy2, w1, h1, area1, at1,
                          d.x, d.y, d.z, d.w);
    }
    if (tid < KK) s_ciou[tid] = my_ciou;
    __syncthreads();
    if (tid == 0) {
        float m = 0.0f;
#pragma unroll
        for (int i = 0; i < KK; i++) m = fmaxf(m, s_ciou[i]);
        s_maxovl = m;
    }
    __syncthreads();
    if (my_a >= 0) {
        float max_align = __uint_as_float((unsigned int)(winners[0] >> 32));
        float normv = __fdiv_rn(my_align * s_maxovl, max_align + FEPS);
        unsigned long long akey =
            ((unsigned long long)__float_as_uint(my_ciou) << 32) |
            (unsigned int)(GG - 1 - g);  // tie-break: smaller g wins
        atomicMax(&g_key[(size_t)b * AA + my_a], akey);
        atomicMax(&g_normb[(size_t)b * AA + my_a], __float_as_uint(normv));
    }
}

// ---------------------------------------------------------------------------
// finalize: one warp per anchor; coalesced writes of all outputs.
// Output layout: bbox[B,A,4] | cls_oh[B,A,C] | dist[B,A,1] | fg[B,A]
// ---------------------------------------------------------------------------
__global__ __launch_bounds__(256) void finalize_kernel(
    const int* __restrict__ gt_labels, const float* __restrict__ gt_bboxes,
    const float* __restrict__ gt_dist, float* __restrict__ out)
{
    int warp = blockIdx.x * 8 + (threadIdx.x >> 5);
    int lane = threadIdx.x & 31;
    if (warp >= BB * AA) return;
    int b = warp / AA;

    unsigned long long key = g_key[warp];
    float norm = __uint_as_float(g_normb[warp]);
    bool matched = (key != 0ull);
    int gm = matched ? (GG - 1 - (int)(unsigned int)(key & 0xffffffffull)) : 0;
    int base = b * GG + gm;

    float* out_bbox = out;
    float* out_cls  = out + (size_t)BB * AA * 4;
    float* out_dist = out_cls + (size_t)BB * AA * CC;
    float* out_fg   = out_dist + (size_t)BB * AA;

    if (lane < 4)
        out_bbox[(size_t)warp * 4 + lane] =
            matched ? gt_bboxes[base * 4 + lane] : -1.0f;

    int label = matched ? gt_labels[base] : -1;
#pragma unroll
    for (int c = 0; c < CC; c += 32) {
        int cc = c + lane;
        if (cc < CC)
            out_cls[(size_t)warp * CC + cc] = (cc == label) ? norm : 0.0f;
    }
    if (lane == 0) {
        out_dist[warp] = (matched ? gt_dist[base] : -1.0f) * norm;
        out_fg[warp]   = 1.0f;  // gt_match = argmax >= 0 always -> fg == 1
    }
}

// ---------------------------------------------------------------------------
extern "C" void kernel_launch(void* const* d_in, const int* in_sizes, int n_in,
                              void* d_out, int out_size) {
    const float* scores = nullptr;
    const float* dbox = nullptr;
    const float* anchors = nullptr;
    const float* gtb = nullptr;
    const int* gtl = nullptr;
    const float* gtd = nullptr;
    const unsigned char* gmask = nullptr;
    int small_seen = 0;
    for (int i = 0; i < n_in; i++) {
        int s = in_sizes[i];
        if (s == BB * AA * CC)      scores = (const float*)d_in[i];
        else if (s == BB * AA * 4)  dbox = (const float*)d_in[i];
        else if (s == AA * 2)       anchors = (const float*)d_in[i];
        else if (s == BB * GG * 4)  gtb = (const float*)d_in[i];
        else if (s == BB * GG) {
            // metadata order: gt_labels, gt_distances, gt_mask
            if (small_seen == 0)      gtl = (const int*)d_in[i];
            else if (small_seen == 1) gtd = (const float*)d_in[i];
            else                      gmask = (const unsigned char*)d_in[i];
            small_seen++;
        }
        // s == BB*AA: `distances` input, unused by the reference
    }

    init_kernel<<<528, 256>>>(gmask);
    assign_kernel<<<BB * GG, 256>>>(scores, dbox, anchors, gtl, gtb);
    finalize_kernel<<<(BB * AA + 7) / 8, 256>>>(gtl, gtb, gtd, (float*)d_out);
}